// round 6
// baseline (speedup 1.0000x reference)
#include <cuda_runtime.h>
#include <cstdint>

// CachedMPS on GB300 — HMMA tf32 2-split with STEP PAIRING.
//
//  pair p (steps 2p, 2p+1):
//    M' = sum_{ci=0..3} sc[ci] * M * Wcomp[ci],  sc = {c1c2, s1c2, c1s2, s1s2}*rsqrt(|M|)
//    Wcomp[f1+2*f2] = W_{2p,f1} @ W_{2p+1,f2}   (fp32 prep, tf32 hi/lo split)
//  i.e. one k=128 GEMM per pair: A=[scaled M copies][32,128] x Wstack[128,32].
//  3-term tf32 split (hi*hi + hi*lo + lo*hi), f32 accum. MAC count identical to
//  unpaired; per-step shuffle/sync/sincos/rsqrt overhead halved.
//
// Normalization: per-step L2-norm removed (homogeneous chain); rsqrt folded
// into the pair scalars; eps-free final unit-normalize (R1 lesson).

#define DEV_INLINE __device__ __forceinline__

static constexpr int D     = 32;
static constexpr int L     = 256;
static constexpr int NMID  = 254;
static constexpr int NPAIR = 127;
static constexpr int C     = 10;
static constexpr int TPB   = 224;            // 7 warps -> grid 147 fills 148 SMs
static constexpr int ROWS_PER_WARP = 32;
static constexpr int ROWS_PER_CTA  = TPB / 32 * ROWS_PER_WARP;   // 224
static constexpr float HALF_PI = 1.57079632679489662f;

// composite-W scratch: [NPAIR][hi 4096 | lo 4096] floats (frag-native order)
__device__ float g_Bt[(size_t)NPAIR * 8192];

DEV_INLINE unsigned f2tf32(float v) {
    unsigned r; asm("cvt.rna.tf32.f32 %0, %1;" : "=r"(r) : "f"(v)); return r;
}
DEV_INLINE unsigned smem_u32(const void* p) {
    unsigned r;
    asm("{ .reg .u64 t; cvta.to.shared.u64 t, %1; cvt.u32.u64 %0, t; }" : "=r"(r) : "l"(p));
    return r;
}
DEV_INLINE void cp16(unsigned dst, const void* src) {
    asm volatile("cp.async.cg.shared.global [%0], [%1], 16;" :: "r"(dst), "l"(src));
}
DEV_INLINE void cp_commit() { asm volatile("cp.async.commit_group;"); }
DEV_INLINE void cp_wait0()  { asm volatile("cp.async.wait_group 0;" ::: "memory"); }

DEV_INLINE void mma8(float* c, const unsigned* a, unsigned b0, unsigned b1) {
    asm("mma.sync.aligned.m16n8k8.row.col.f32.tf32.tf32.f32 "
        "{%0,%1,%2,%3}, {%4,%5,%6,%7}, {%8,%9}, {%0,%1,%2,%3};"
        : "+f"(c[0]), "+f"(c[1]), "+f"(c[2]), "+f"(c[3])
        : "r"(a[0]), "r"(a[1]), "r"(a[2]), "r"(a[3]), "r"(b0), "r"(b1));
}

// ---- prep: composite products in B-fragment-native order ----
// frag slot (within 4096-float half): i = ((t*2 + jp)*32 + lane)*4 + s,
//   t = k-tile 0..15, j = 2*jp + (s>>1), reg = s&1, q = lane&3, g = lane>>2
//   k = 8t + q + 4*reg (0..127): ci = k>>5, a = k&31;  col c = 8j + g
//   value = Wcomp[ci][a][c] = sum_cc W0[f1][a][cc] * W1[f2][cc][c],
//   f1 = ci&1, f2 = ci>>1  (cores layout: [f][a][c] = f*1024 + a*32 + c)
__global__ void prep_pairs(const float* __restrict__ cores_mid) {
    __shared__ float sW0[2048], sW1[2048];
    const int p = blockIdx.x;
    const float* s0 = cores_mid + (size_t)(2 * p) * 2048;
    const float* s1 = cores_mid + (size_t)(2 * p + 1) * 2048;
    for (int i = threadIdx.x; i < 2048; i += blockDim.x) { sW0[i] = s0[i]; sW1[i] = s1[i]; }
    __syncthreads();

    float* dst = g_Bt + (size_t)p * 8192;
    for (int i = threadIdx.x; i < 4096; i += blockDim.x) {
        const int s = i & 3, lane = (i >> 2) & 31, tp = i >> 7;
        const int t = tp >> 1, jp = tp & 1;
        const int j = 2 * jp + (s >> 1), reg = s & 1;
        const int q = lane & 3, g = lane >> 2;
        const int k = 8 * t + q + 4 * reg;
        const int c = 8 * j + g;
        const int ci = k >> 5, a = k & 31;
        const float* r0 = sW0 + (ci & 1) * 1024 + a * 32;
        const float* r1 = sW1 + (ci >> 1) * 1024 + c;
        float v = 0.f;
        #pragma unroll 8
        for (int cc = 0; cc < 32; cc++) v += r0[cc] * r1[cc * 32];
        const unsigned hi = f2tf32(v);
        dst[i]        = __uint_as_float(hi);
        dst[4096 + i] = __uint_as_float(f2tf32(v - __uint_as_float(hi)));
    }
}

__global__ void __launch_bounds__(TPB, 1)
mps_hmma_kernel(const float* __restrict__ x,
                const float* __restrict__ core0,
                const float* __restrict__ coreN,
                float* __restrict__ out, int B)
{
    __shared__ __align__(16) float sW[2][8192];   // 2 stages x (hi 16KB | lo 16KB)

    const int tid  = threadIdx.x;
    const int lane = tid & 31;
    const int w    = tid >> 5;
    const int q    = lane & 3;
    const int g    = lane >> 2;
    const int rowbase = blockIdx.x * ROWS_PER_CTA + w * ROWS_PER_WARP;

    // lane's 4 rows: rid = mt*2 + rowsel -> row = rowbase + 16mt + g + 8*rowsel
    int rows[4];
    #pragma unroll
    for (int rid = 0; rid < 4; rid++) {
        int r = rowbase + (rid >> 1) * 16 + g + (rid & 1) * 8;
        rows[rid] = (r < B) ? r : (B - 1);
    }

    // prefetch pair-0 stack (32KB = 2048 x 16B)
    {
        const float* gsrc = g_Bt;
        const unsigned sb = smem_u32(&sW[0][0]);
        #pragma unroll
        for (int i = 0; i < 10; i++) {
            const int idx = tid + i * TPB;
            if (idx < 2048) cp16(sb + idx * 16, gsrc + idx * 4);
        }
        cp_commit();
    }

    // ---- init acc = M0 in c-frag layout: row g+8*rowsel(+16mt), col 8j+2q+p ----
    float acc[2][16];
    #pragma unroll
    for (int rid = 0; rid < 4; rid++) {
        float s0, c0;
        __sincosf(HALF_PI * __ldg(x + (size_t)rows[rid] * L), &s0, &c0);
        const int mt = rid >> 1, rowsel = rid & 1;
        #pragma unroll
        for (int j = 0; j < 4; j++)
            #pragma unroll
            for (int pp = 0; pp < 2; pp++) {
                const int col = 8 * j + 2 * q + pp;
                acc[mt][4 * j + 2 * rowsel + pp] = c0 * core0[col] + s0 * core0[32 + col];
            }
    }

    // ---- 127 composite steps ----
    for (int p = 0; p < NPAIR; p++) {
        cp_wait0();
        __syncthreads();

        if (p + 1 < NPAIR) {
            const float* gsrc = g_Bt + (size_t)(p + 1) * 8192;
            const unsigned sb = smem_u32(&sW[(p + 1) & 1][0]);
            #pragma unroll
            for (int i = 0; i < 10; i++) {
                const int idx = tid + i * TPB;
                if (idx < 2048) cp16(sb + idx * 16, gsrc + idx * 4);
            }
            cp_commit();
        }

        // pair scalars: sc[ci][rid], ci = f1 + 2*f2; rsqrt(range) folded in
        float sc[4][4];
        #pragma unroll
        for (int rid = 0; rid < 4; rid++) {
            const int mt = rid >> 1, rowsel = rid & 1;
            float ss = 0.f;
            #pragma unroll
            for (int j = 0; j < 4; j++) {
                float v0 = acc[mt][4 * j + 2 * rowsel];
                float v1 = acc[mt][4 * j + 2 * rowsel + 1];
                ss += v0 * v0 + v1 * v1;
            }
            ss += __shfl_xor_sync(0xffffffffu, ss, 1);
            ss += __shfl_xor_sync(0xffffffffu, ss, 2);
            const float rs = rsqrtf(ss);
            float s1v, c1v, s2v, c2v;
            __sincosf(HALF_PI * __ldg(x + (size_t)rows[rid] * L + (2 * p + 1)), &s1v, &c1v);
            __sincosf(HALF_PI * __ldg(x + (size_t)rows[rid] * L + (2 * p + 2)), &s2v, &c2v);
            sc[0][rid] = c1v * c2v * rs;
            sc[1][rid] = s1v * c2v * rs;
            sc[2][rid] = c1v * s2v * rs;
            sc[3][rid] = s1v * s2v * rs;
        }

        // gather raw M a-frags (one pass; a-reg i: row g+8*(i&1), kcol 8tt+q+4*(i>>1))
        float av[2][4][4];
        #pragma unroll
        for (int mt = 0; mt < 2; mt++)
            #pragma unroll
            for (int tt = 0; tt < 4; tt++)
                #pragma unroll
                for (int i = 0; i < 4; i++) {
                    const int rowsel = i & 1, khalf = i >> 1;
                    const int srcLane = 4 * g + (q >> 1) + 2 * khalf;
                    const float v0 = __shfl_sync(0xffffffffu,
                                                 acc[mt][4 * tt + 2 * rowsel], srcLane);
                    const float v1 = __shfl_sync(0xffffffffu,
                                                 acc[mt][4 * tt + 2 * rowsel + 1], srcLane);
                    av[mt][tt][i] = (q & 1) ? v1 : v0;
                }

        // zero acc, accumulate the k=128 pair-GEMM in place
        #pragma unroll
        for (int mt = 0; mt < 2; mt++)
            #pragma unroll
            for (int k = 0; k < 16; k++) acc[mt][k] = 0.f;

        const float* Whi = &sW[p & 1][0];
        const float* Wlo = &sW[p & 1][4096];

        #pragma unroll
        for (int t = 0; t < 16; t++) {
            const int ci = t >> 2, tt = t & 3;
            float bh[2][4], bl[2][4];
            #pragma unroll
            for (int jp = 0; jp < 2; jp++) {
                const int fi = ((t * 2 + jp) * 32 + lane) * 4;
                const float4 vh = *reinterpret_cast<const float4*>(Whi + fi);
                const float4 vl = *reinterpret_cast<const float4*>(Wlo + fi);
                bh[jp][0] = vh.x; bh[jp][1] = vh.y; bh[jp][2] = vh.z; bh[jp][3] = vh.w;
                bl[jp][0] = vl.x; bl[jp][1] = vl.y; bl[jp][2] = vl.z; bl[jp][3] = vl.w;
            }
            #pragma unroll
            for (int mt = 0; mt < 2; mt++) {
                unsigned ahi[4], alo[4];
                #pragma unroll
                for (int i = 0; i < 4; i++) {
                    const int rid = mt * 2 + (i & 1);
                    const float v = av[mt][tt][i] * sc[ci][rid];
                    ahi[i] = f2tf32(v);
                    alo[i] = f2tf32(v - __uint_as_float(ahi[i]));
                }
                #pragma unroll
                for (int j = 0; j < 4; j++) {
                    const int jp = j >> 1, e = (j & 1) * 2;
                    const unsigned b0h = __float_as_uint(bh[jp][e]);
                    const unsigned b1h = __float_as_uint(bh[jp][e + 1]);
                    const unsigned b0l = __float_as_uint(bl[jp][e]);
                    const unsigned b1l = __float_as_uint(bl[jp][e + 1]);
                    mma8(&acc[mt][4 * j], ahi, b0h, b1h);   // hi*Whi
                    mma8(&acc[mt][4 * j], ahi, b0l, b1l);   // hi*Wlo
                    mma8(&acc[mt][4 * j], alo, b0h, b1h);   // lo*Whi
                }
            }
        }
    }

    // ---- readout: eps-free unit normalize + coreN contraction ----
    #pragma unroll
    for (int rid = 0; rid < 4; rid++) {
        const int mt = rid >> 1, rowsel = rid & 1;
        const int row = rowbase + mt * 16 + g + 8 * rowsel;

        float ss = 0.f;
        #pragma unroll
        for (int j = 0; j < 4; j++) {
            float v0 = acc[mt][4 * j + 2 * rowsel];
            float v1 = acc[mt][4 * j + 2 * rowsel + 1];
            ss += v0 * v0 + v1 * v1;
        }
        ss += __shfl_xor_sync(0xffffffffu, ss, 1);
        ss += __shfl_xor_sync(0xffffffffu, ss, 2);
        const float inv = rsqrtf(ss);           // NO eps (R1 lesson)

        float sL, cL;
        __sincosf(HALF_PI * __ldg(x + (size_t)rows[rid] * L + (L - 1)), &sL, &cL);

        float lg[C];
        #pragma unroll
        for (int cc = 0; cc < C; cc++) lg[cc] = 0.f;
        #pragma unroll
        for (int j = 0; j < 4; j++)
            #pragma unroll
            for (int pp = 0; pp < 2; pp++) {
                const int col = 8 * j + 2 * q + pp;
                const float m = acc[mt][4 * j + 2 * rowsel + pp];
                #pragma unroll
                for (int cc = 0; cc < C; cc++) {
                    const float wv = cL * coreN[col * C + cc]
                                   + sL * coreN[D * C + col * C + cc];
                    lg[cc] += m * wv;
                }
            }
        #pragma unroll
        for (int cc = 0; cc < C; cc++) {
            lg[cc] += __shfl_xor_sync(0xffffffffu, lg[cc], 1);
            lg[cc] += __shfl_xor_sync(0xffffffffu, lg[cc], 2);
        }
        if (q == 0 && row < B) {
            #pragma unroll
            for (int cc = 0; cc < C; cc++)
                out[(size_t)row * C + cc] = lg[cc] * inv;
        }
    }
}

extern "C" void kernel_launch(void* const* d_in, const int* in_sizes, int n_in,
                              void* d_out, int out_size)
{
    const float* x         = (const float*)d_in[0];
    const float* core0     = (const float*)d_in[1];
    const float* cores_mid = (const float*)d_in[2];
    const float* coreN     = (const float*)d_in[3];
    float* out = (float*)d_out;

    const int B = in_sizes[0] / L;
    const int grid = (B + ROWS_PER_CTA - 1) / ROWS_PER_CTA;   // 147 for B=32768

    prep_pairs<<<NPAIR, 256>>>(cores_mid);
    mps_hmma_kernel<<<grid, TPB>>>(x, core0, coreN, out, B);
}

// round 7
// speedup vs baseline: 1.0723x; 1.0723x over previous
#include <cuda_runtime.h>
#include <cstdint>

// CachedMPS on GB300 — HMMA tf32 2-split, paired steps, m16 tiles.
// R7: 16 rows/warp (2048 warps -> 3.46/SMSP), 2 CTAs/SM, lo-term cvt dropped
// (raw f32 residual; MMA tf32 truncation error ~2^-22 of product).
//
//  pair p: M' = sum_ci sc[ci] * M * Wcomp[ci], one k=128 GEMM, 3-term tf32 split.
//  Homogeneous chain: per-step L2-norm removed; rsqrt folded into sc; eps-free
//  final unit-normalize.

#define DEV_INLINE __device__ __forceinline__

static constexpr int D     = 32;
static constexpr int L     = 256;
static constexpr int NPAIR = 127;
static constexpr int C     = 10;
static constexpr int TPB   = 256;             // 8 warps x 16 rows = 128 rows/CTA
static constexpr int ROWS_PER_WARP = 16;
static constexpr int ROWS_PER_CTA  = TPB / 32 * ROWS_PER_WARP;   // 128
static constexpr float HALF_PI = 1.57079632679489662f;

// composite-W scratch: [NPAIR][hi 4096 | lo 4096] floats (frag-native order)
__device__ float g_Bt[(size_t)NPAIR * 8192];

DEV_INLINE unsigned f2tf32(float v) {
    unsigned r; asm("cvt.rna.tf32.f32 %0, %1;" : "=r"(r) : "f"(v)); return r;
}
DEV_INLINE unsigned smem_u32(const void* p) {
    unsigned r;
    asm("{ .reg .u64 t; cvta.to.shared.u64 t, %1; cvt.u32.u64 %0, t; }" : "=r"(r) : "l"(p));
    return r;
}
DEV_INLINE void cp16(unsigned dst, const void* src) {
    asm volatile("cp.async.cg.shared.global [%0], [%1], 16;" :: "r"(dst), "l"(src));
}
DEV_INLINE void cp_commit() { asm volatile("cp.async.commit_group;"); }
DEV_INLINE void cp_wait0()  { asm volatile("cp.async.wait_group 0;" ::: "memory"); }

DEV_INLINE void mma8(float* c, const unsigned* a, unsigned b0, unsigned b1) {
    asm("mma.sync.aligned.m16n8k8.row.col.f32.tf32.tf32.f32 "
        "{%0,%1,%2,%3}, {%4,%5,%6,%7}, {%8,%9}, {%0,%1,%2,%3};"
        : "+f"(c[0]), "+f"(c[1]), "+f"(c[2]), "+f"(c[3])
        : "r"(a[0]), "r"(a[1]), "r"(a[2]), "r"(a[3]), "r"(b0), "r"(b1));
}

// ---- prep: composite pair products, B-fragment-native order (verified R6) ----
// slot i = ((t*2 + jp)*32 + lane)*4 + s: t=k-tile 0..15, j=2*jp+(s>>1), reg=s&1,
// q=lane&3, g=lane>>2; k = 8t+q+4*reg; ci=k>>5; a=k&31; col c=8j+g
// value = sum_cc W0[ci&1][a][cc] * W1[ci>>1][cc][c]
__global__ void prep_pairs(const float* __restrict__ cores_mid) {
    __shared__ float sW0[2048], sW1[2048];
    const int p = blockIdx.x;
    const float* s0 = cores_mid + (size_t)(2 * p) * 2048;
    const float* s1 = cores_mid + (size_t)(2 * p + 1) * 2048;
    for (int i = threadIdx.x; i < 2048; i += blockDim.x) { sW0[i] = s0[i]; sW1[i] = s1[i]; }
    __syncthreads();

    float* dst = g_Bt + (size_t)p * 8192;
    for (int i = threadIdx.x; i < 4096; i += blockDim.x) {
        const int s = i & 3, lane = (i >> 2) & 31, tp = i >> 7;
        const int t = tp >> 1, jp = tp & 1;
        const int j = 2 * jp + (s >> 1), reg = s & 1;
        const int q = lane & 3, g = lane >> 2;
        const int k = 8 * t + q + 4 * reg;
        const int c = 8 * j + g;
        const int ci = k >> 5, a = k & 31;
        const float* r0 = sW0 + (ci & 1) * 1024 + a * 32;
        const float* r1 = sW1 + (ci >> 1) * 1024 + c;
        float v = 0.f;
        #pragma unroll 8
        for (int cc = 0; cc < 32; cc++) v += r0[cc] * r1[cc * 32];
        const unsigned hi = f2tf32(v);
        dst[i]        = __uint_as_float(hi);
        dst[4096 + i] = __uint_as_float(f2tf32(v - __uint_as_float(hi)));
    }
}

__global__ void __launch_bounds__(TPB, 2)
mps_hmma_kernel(const float* __restrict__ x,
                const float* __restrict__ core0,
                const float* __restrict__ coreN,
                float* __restrict__ out, int B)
{
    __shared__ __align__(16) float sW[2][8192];   // 2 stages x (hi 16KB | lo 16KB)

    const int tid  = threadIdx.x;
    const int lane = tid & 31;
    const int w    = tid >> 5;
    const int q    = lane & 3;
    const int g    = lane >> 2;
    const int rowbase = blockIdx.x * ROWS_PER_CTA + w * ROWS_PER_WARP;

    // lane's 2 rows: rowsel 0 -> g, 1 -> g+8
    int rows[2];
    rows[0] = min(rowbase + g,     B - 1);
    rows[1] = min(rowbase + g + 8, B - 1);

    // prefetch pair-0 stack (32KB = 2048 x 16B, 8 per thread)
    {
        const float* gsrc = g_Bt;
        const unsigned sb = smem_u32(&sW[0][0]);
        #pragma unroll
        for (int i = 0; i < 8; i++) {
            const int idx = tid + i * TPB;
            cp16(sb + idx * 16, gsrc + idx * 4);
        }
        cp_commit();
    }

    // ---- init acc = M0, c-frag layout: acc[4j+2*rowsel+p] = M[g+8rs][8j+2q+p] ----
    float acc[16];
    #pragma unroll
    for (int rs = 0; rs < 2; rs++) {
        float s0, c0;
        __sincosf(HALF_PI * __ldg(x + (size_t)rows[rs] * L), &s0, &c0);
        #pragma unroll
        for (int j = 0; j < 4; j++)
            #pragma unroll
            for (int pp = 0; pp < 2; pp++) {
                const int col = 8 * j + 2 * q + pp;
                acc[4 * j + 2 * rs + pp] = c0 * core0[col] + s0 * core0[32 + col];
            }
    }

    // ---- 127 composite steps ----
    for (int p = 0; p < NPAIR; p++) {
        cp_wait0();
        __syncthreads();

        if (p + 1 < NPAIR) {
            const float* gsrc = g_Bt + (size_t)(p + 1) * 8192;
            const unsigned sb = smem_u32(&sW[(p + 1) & 1][0]);
            #pragma unroll
            for (int i = 0; i < 8; i++) {
                const int idx = tid + i * TPB;
                cp16(sb + idx * 16, gsrc + idx * 4);
            }
            cp_commit();
        }

        // pair scalars sc[ci][rowsel], rsqrt(range) folded in
        float sc[4][2];
        #pragma unroll
        for (int rs = 0; rs < 2; rs++) {
            float ss = 0.f;
            #pragma unroll
            for (int j = 0; j < 4; j++) {
                const float v0 = acc[4 * j + 2 * rs];
                const float v1 = acc[4 * j + 2 * rs + 1];
                ss += v0 * v0 + v1 * v1;
            }
            ss += __shfl_xor_sync(0xffffffffu, ss, 1);
            ss += __shfl_xor_sync(0xffffffffu, ss, 2);
            const float r = rsqrtf(ss);
            float s1v, c1v, s2v, c2v;
            __sincosf(HALF_PI * __ldg(x + (size_t)rows[rs] * L + (2 * p + 1)), &s1v, &c1v);
            __sincosf(HALF_PI * __ldg(x + (size_t)rows[rs] * L + (2 * p + 2)), &s2v, &c2v);
            sc[0][rs] = c1v * c2v * r;
            sc[1][rs] = s1v * c2v * r;
            sc[2][rs] = c1v * s2v * r;
            sc[3][rs] = s1v * s2v * r;
        }

        // gather raw a-frags from c-frags (verified lane algebra from R5/R6):
        // av[tt][i]: row g+8*(i&1), col 8tt + q + 4*(i>>1)
        float av[4][4];
        const int sl = 4 * g + (q >> 1);
        #pragma unroll
        for (int tt = 0; tt < 4; tt++) {
            const float v0a = __shfl_sync(0xffffffffu, acc[4 * tt],     sl);
            const float v1a = __shfl_sync(0xffffffffu, acc[4 * tt + 1], sl);
            const float v0b = __shfl_sync(0xffffffffu, acc[4 * tt + 2], sl);
            const float v1b = __shfl_sync(0xffffffffu, acc[4 * tt + 3], sl);
            const float w0a = __shfl_sync(0xffffffffu, acc[4 * tt],     sl + 2);
            const float w1a = __shfl_sync(0xffffffffu, acc[4 * tt + 1], sl + 2);
            const float w0b = __shfl_sync(0xffffffffu, acc[4 * tt + 2], sl + 2);
            const float w1b = __shfl_sync(0xffffffffu, acc[4 * tt + 3], sl + 2);
            const bool odd = (q & 1);
            av[tt][0] = odd ? v1a : v0a;
            av[tt][1] = odd ? v1b : v0b;
            av[tt][2] = odd ? w1a : w0a;
            av[tt][3] = odd ? w1b : w0b;
        }

        #pragma unroll
        for (int k = 0; k < 16; k++) acc[k] = 0.f;

        const float* Whi = &sW[p & 1][0];
        const float* Wlo = &sW[p & 1][4096];

        #pragma unroll
        for (int t = 0; t < 16; t++) {
            const int ci = t >> 2, tt = t & 3;
            float4 bh0 = *reinterpret_cast<const float4*>(Whi + ((t * 2 + 0) * 32 + lane) * 4);
            float4 bh1 = *reinterpret_cast<const float4*>(Whi + ((t * 2 + 1) * 32 + lane) * 4);
            float4 bl0 = *reinterpret_cast<const float4*>(Wlo + ((t * 2 + 0) * 32 + lane) * 4);
            float4 bl1 = *reinterpret_cast<const float4*>(Wlo + ((t * 2 + 1) * 32 + lane) * 4);

            unsigned ahi[4], alo[4];
            #pragma unroll
            for (int i = 0; i < 4; i++) {
                const float v = av[tt][i] * sc[ci][i & 1];
                ahi[i] = f2tf32(v);
                // lo passed RAW (no cvt): MMA truncation error ~2^-22 of product
                alo[i] = __float_as_uint(v - __uint_as_float(ahi[i]));
            }

            const float bhv[2][4] = {{bh0.x, bh0.y, bh0.z, bh0.w},
                                     {bh1.x, bh1.y, bh1.z, bh1.w}};
            const float blv[2][4] = {{bl0.x, bl0.y, bl0.z, bl0.w},
                                     {bl1.x, bl1.y, bl1.z, bl1.w}};
            #pragma unroll
            for (int j = 0; j < 4; j++) {
                const int jp = j >> 1, e = (j & 1) * 2;
                const unsigned b0h = __float_as_uint(bhv[jp][e]);
                const unsigned b1h = __float_as_uint(bhv[jp][e + 1]);
                const unsigned b0l = __float_as_uint(blv[jp][e]);
                const unsigned b1l = __float_as_uint(blv[jp][e + 1]);
                mma8(&acc[4 * j], ahi, b0h, b1h);   // hi*Whi
                mma8(&acc[4 * j], ahi, b0l, b1l);   // hi*Wlo
                mma8(&acc[4 * j], alo, b0h, b1h);   // lo*Whi
            }
        }
    }

    // ---- readout: eps-free unit normalize + coreN contraction ----
    #pragma unroll
    for (int rs = 0; rs < 2; rs++) {
        const int row = rowbase + g + 8 * rs;

        float ss = 0.f;
        #pragma unroll
        for (int j = 0; j < 4; j++) {
            const float v0 = acc[4 * j + 2 * rs];
            const float v1 = acc[4 * j + 2 * rs + 1];
            ss += v0 * v0 + v1 * v1;
        }
        ss += __shfl_xor_sync(0xffffffffu, ss, 1);
        ss += __shfl_xor_sync(0xffffffffu, ss, 2);
        const float inv = rsqrtf(ss);           // NO eps (R1 lesson)

        float sL, cL;
        __sincosf(HALF_PI * __ldg(x + (size_t)rows[rs] * L + (L - 1)), &sL, &cL);

        float lg[C];
        #pragma unroll
        for (int cc = 0; cc < C; cc++) lg[cc] = 0.f;
        #pragma unroll
        for (int j = 0; j < 4; j++)
            #pragma unroll
            for (int pp = 0; pp < 2; pp++) {
                const int col = 8 * j + 2 * q + pp;
                const float m = acc[4 * j + 2 * rs + pp];
                #pragma unroll
                for (int cc = 0; cc < C; cc++) {
                    const float wv = cL * coreN[col * C + cc]
                                   + sL * coreN[D * C + col * C + cc];
                    lg[cc] += m * wv;
                }
            }
        #pragma unroll
        for (int cc = 0; cc < C; cc++) {
            lg[cc] += __shfl_xor_sync(0xffffffffu, lg[cc], 1);
            lg[cc] += __shfl_xor_sync(0xffffffffu, lg[cc], 2);
        }
        if (q == 0 && row < B) {
            #pragma unroll
            for (int cc = 0; cc < C; cc++)
                out[(size_t)row * C + cc] = lg[cc] * inv;
        }
    }
}

extern "C" void kernel_launch(void* const* d_in, const int* in_sizes, int n_in,
                              void* d_out, int out_size)
{
    const float* x         = (const float*)d_in[0];
    const float* core0     = (const float*)d_in[1];
    const float* cores_mid = (const float*)d_in[2];
    const float* coreN     = (const float*)d_in[3];
    float* out = (float*)d_out;

    const int B = in_sizes[0] / L;
    const int grid = (B + ROWS_PER_CTA - 1) / ROWS_PER_CTA;   // 256 for B=32768

    prep_pairs<<<NPAIR, 256>>>(cores_mid);
    mps_hmma_kernel<<<grid, TPB>>>(x, core0, coreN, out, B);
}